// round 2
// baseline (speedup 1.0000x reference)
#include <cuda_runtime.h>
#include <math.h>
#include <stdint.h>

#define HDIM   1024
#define TSTEPS 256
#define VOCAB  50257

// ---------------- recurrence config ----------------
#define RNN_NB      64          // co-resident blocks (<148 SMs)
#define RNN_THREADS 512         // 16 warps -> 16 rows per block
#define ROWS_PER_BLK (HDIM / RNN_NB)   // 16

// -------- device scratch (no allocations allowed) --------
__device__ __align__(16) float g_X[TSTEPS * HDIM];   // Wxh[:, c_t] + bh
__device__ __align__(16) float g_H[TSTEPS * HDIM];   // hidden states h_t
__device__ volatile unsigned g_flags[RNN_NB];        // per-block barrier flags

// ---------------- init: reset flags every launch (graph-replay determinism)
__global__ void init_kernel() {
    if (threadIdx.x < RNN_NB) g_flags[threadIdx.x] = 0u;
}

// ---------------- gather: g_X[t][h] = Wxh[h][c_t] + bh[h]
__global__ void gather_x_kernel(const int* __restrict__ chars,
                                const float* __restrict__ Wxh,
                                const float* __restrict__ bh) {
    int t = blockIdx.x;
    int h = blockIdx.y * blockDim.x + threadIdx.x;
    int c = chars[t];
    g_X[t * HDIM + h] = Wxh[(size_t)h * VOCAB + c] + bh[h];
}

// ---------------- phase 1: sequential recurrence, persistent kernel.
// 64 blocks x 16 warps; each warp owns one Whh row in registers.
// Grid barrier: per-block flag array (NO same-address atomics).
__global__ void __launch_bounds__(RNN_THREADS, 1)
rnn_steps_kernel(const float* __restrict__ Whh, const float* __restrict__ h0) {
    __shared__ float sh[HDIM];
    const int warp = threadIdx.x >> 5;
    const int lane = threadIdx.x & 31;
    const int row  = blockIdx.x * ROWS_PER_BLK + warp;

    // This warp's Whh row in registers: 8 float4 per lane.
    float4 w[8];
    const float4* wrow = reinterpret_cast<const float4*>(Whh + (size_t)row * HDIM);
#pragma unroll
    for (int j = 0; j < 8; ++j) w[j] = wrow[j * 32 + lane];

    // stage h0
    reinterpret_cast<float2*>(sh)[threadIdx.x] =
        reinterpret_cast<const float2*>(h0)[threadIdx.x];
    __syncthreads();

    for (int t = 0; t < TSTEPS; ++t) {
        float acc = 0.f;
#pragma unroll
        for (int j = 0; j < 8; ++j) {
            float4 hv = reinterpret_cast<const float4*>(sh)[j * 32 + lane];
            acc += w[j].x * hv.x + w[j].y * hv.y + w[j].z * hv.z + w[j].w * hv.w;
        }
#pragma unroll
        for (int o = 16; o > 0; o >>= 1)
            acc += __shfl_down_sync(0xffffffffu, acc, o);

        if (lane == 0)
            g_H[(size_t)t * HDIM + row] = tanhf(acc + g_X[(size_t)t * HDIM + row]);

        // ---- distributed grid barrier: flag-array, no atomic contention
        __threadfence();
        __syncthreads();
        if (threadIdx.x < RNN_NB) {
            if (threadIdx.x == 0) g_flags[blockIdx.x] = (unsigned)(t + 1);
            while (g_flags[threadIdx.x] < (unsigned)(t + 1)) { }
        }
        __syncthreads();

        // stage h_t for next step
        reinterpret_cast<float2*>(sh)[threadIdx.x] =
            reinterpret_cast<const float2*>(g_H + (size_t)t * HDIM)[threadIdx.x];
        __syncthreads();
    }
}

// ---------------- phase 2: tensor-core (tf32 mma) GEMM
// logits[t][v] = sum_k Why[v][k] * H[t][k] + by[v]
// BM=128 (vocab), BN=256 (ALL time steps -> Why streamed exactly once), BK=32.
// 512 threads = 16 warps in 4(m) x 4(n); warp tile 32x64; mma m16n8k8 tf32.
#define BM 128
#define BN 256
#define BK 32
#define GEMM_THREADS 512
#define APITCH 36              // floats per smem row (16B aligned, conflict-free frags)
#define BPITCH 36
#define A_FLOATS (BM * APITCH)               // 4608
#define B_FLOATS (BN * BPITCH)               // 9216
#define STAGE_FLOATS (A_FLOATS + B_FLOATS)   // 13824
#define GEMM_SMEM_BYTES (2 * STAGE_FLOATS * 4)  // 110592

__device__ __forceinline__ void cp16(uint32_t sdst, const void* gsrc) {
    asm volatile("cp.async.cg.shared.global [%0], [%1], 16;\n" :: "r"(sdst), "l"(gsrc));
}
__device__ __forceinline__ void cp_commit() {
    asm volatile("cp.async.commit_group;\n");
}
template <int N>
__device__ __forceinline__ void cp_wait() {
    asm volatile("cp.async.wait_group %0;\n" :: "n"(N));
}

__device__ __forceinline__ void mma_tf32(float d[4], const uint32_t a[4], const uint32_t b[2]) {
    asm volatile(
        "mma.sync.aligned.m16n8k8.row.col.f32.tf32.tf32.f32 "
        "{%0,%1,%2,%3}, {%4,%5,%6,%7}, {%8,%9}, {%0,%1,%2,%3};\n"
        : "+f"(d[0]), "+f"(d[1]), "+f"(d[2]), "+f"(d[3])
        : "r"(a[0]), "r"(a[1]), "r"(a[2]), "r"(a[3]), "r"(b[0]), "r"(b[1]));
}

extern __shared__ float g_smem[];

__global__ void __launch_bounds__(GEMM_THREADS, 1)
gemm_logits_kernel(const float* __restrict__ Why,
                   const float* __restrict__ by,
                   float* __restrict__ out) {
    const int tid  = threadIdx.x;
    const int lane = tid & 31;
    const int wid  = tid >> 5;
    const int wm   = wid & 3;        // warp m index (0..3) -> 32 vocab rows
    const int wn   = wid >> 2;       // warp n index (0..3) -> 64 time cols
    const int m0   = blockIdx.x * BM;

    const uint32_t smem_u = (uint32_t)__cvta_generic_to_shared(g_smem);

    // ---- tile loader (cp.async): A rows are Why rows (clamped at vocab tail)
    auto load_tile = [&](int stage, int k0) {
        uint32_t sa = smem_u + (uint32_t)(stage * STAGE_FLOATS) * 4u;
        uint32_t sb = sa + (uint32_t)A_FLOATS * 4u;
        // A: 128 rows x 8 chunks of 16B = 1024 ops -> 2 per thread
#pragma unroll
        for (int q = 0; q < 2; ++q) {
            int i = tid + q * GEMM_THREADS;
            int row = i >> 3, ch = i & 7;
            int gm = m0 + row; if (gm > VOCAB - 1) gm = VOCAB - 1;
            cp16(sa + (uint32_t)(row * APITCH + ch * 4) * 4u,
                 Why + (size_t)gm * HDIM + k0 + ch * 4);
        }
        // B: 256 rows x 8 chunks = 2048 ops -> 4 per thread
#pragma unroll
        for (int q = 0; q < 4; ++q) {
            int i = tid + q * GEMM_THREADS;
            int row = i >> 3, ch = i & 7;
            cp16(sb + (uint32_t)(row * BPITCH + ch * 4) * 4u,
                 g_H + (size_t)row * HDIM + k0 + ch * 4);
        }
        cp_commit();
    };

    float acc[2][8][4] = {};

    load_tile(0, 0);

    const int r = lane >> 2;   // group id
    const int c = lane & 3;    // thread-in-group

    for (int kt = 0; kt < HDIM / BK; ++kt) {
        const int cur = kt & 1;
        if (kt + 1 < HDIM / BK) {
            load_tile(cur ^ 1, (kt + 1) * BK);
            cp_wait<1>();
        } else {
            cp_wait<0>();
        }
        __syncthreads();

        const float* As = g_smem + cur * STAGE_FLOATS;
        const float* Bs = As + A_FLOATS;

#pragma unroll
        for (int ki = 0; ki < BK / 8; ++ki) {
            uint32_t a[2][4], b[8][2];
            const int kk = ki * 8 + c;
#pragma unroll
            for (int mi = 0; mi < 2; ++mi) {
                const int mr = wm * 32 + mi * 16 + r;
                a[mi][0] = __float_as_uint(As[(mr    ) * APITCH + kk    ]);
                a[mi][1] = __float_as_uint(As[(mr + 8) * APITCH + kk    ]);
                a[mi][2] = __float_as_uint(As[(mr    ) * APITCH + kk + 4]);
                a[mi][3] = __float_as_uint(As[(mr + 8) * APITCH + kk + 4]);
            }
#pragma unroll
            for (int nf = 0; nf < 8; ++nf) {
                const int nc = wn * 64 + nf * 8 + r;
                b[nf][0] = __float_as_uint(Bs[nc * BPITCH + kk    ]);
                b[nf][1] = __float_as_uint(Bs[nc * BPITCH + kk + 4]);
            }
#pragma unroll
            for (int mi = 0; mi < 2; ++mi)
#pragma unroll
                for (int nf = 0; nf < 8; ++nf)
                    mma_tf32(acc[mi][nf], a[mi], b[nf]);
        }
        __syncthreads();
    }

    // ---- epilogue: out[t][v] = acc + by[v]
#pragma unroll
    for (int mi = 0; mi < 2; ++mi) {
        const int v0 = m0 + wm * 32 + mi * 16 + r;
        const int v1 = v0 + 8;
        const float bias0 = (v0 < VOCAB) ? by[v0] : 0.f;
        const float bias1 = (v1 < VOCAB) ? by[v1] : 0.f;
#pragma unroll
        for (int nf = 0; nf < 8; ++nf) {
            const int t0 = wn * 64 + nf * 8 + c * 2;
            const int t1 = t0 + 1;
            if (v0 < VOCAB) {
                out[(size_t)t0 * VOCAB + v0] = acc[mi][nf][0] + bias0;
                out[(size_t)t1 * VOCAB + v0] = acc[mi][nf][1] + bias0;
            }
            if (v1 < VOCAB) {
                out[(size_t)t0 * VOCAB + v1] = acc[mi][nf][2] + bias1;
                out[(size_t)t1 * VOCAB + v1] = acc[mi][nf][3] + bias1;
            }
        }
    }
}

// ---------------- phase 3: in-place stable softmax over each row of 50257
__global__ void __launch_bounds__(1024) softmax_rows_kernel(float* __restrict__ out) {
    __shared__ float red[1024];
    const int t = blockIdx.x;
    float* row = out + (size_t)t * VOCAB;
    const int tid = threadIdx.x;

    float m = -1e30f;
    for (int i = tid; i < VOCAB; i += 1024) m = fmaxf(m, row[i]);
    red[tid] = m; __syncthreads();
    for (int s = 512; s > 0; s >>= 1) {
        if (tid < s) red[tid] = fmaxf(red[tid], red[tid + s]);
        __syncthreads();
    }
    m = red[0];
    __syncthreads();

    float sum = 0.f;
    for (int i = tid; i < VOCAB; i += 1024) sum += expf(row[i] - m);
    red[tid] = sum; __syncthreads();
    for (int s = 512; s > 0; s >>= 1) {
        if (tid < s) red[tid] += red[tid + s];
        __syncthreads();
    }
    float inv = 1.0f / red[0];
    __syncthreads();

    for (int i = tid; i < VOCAB; i += 1024) row[i] = expf(row[i] - m) * inv;
}

// ---------------- launch ----------------
extern "C" void kernel_launch(void* const* d_in, const int* in_sizes, int n_in,
                              void* d_out, int out_size) {
    const int*   chars = (const int*)  d_in[0];
    const float* Wxh   = (const float*)d_in[1];
    const float* Whh   = (const float*)d_in[2];
    const float* Why   = (const float*)d_in[3];
    const float* bh    = (const float*)d_in[4];
    const float* by    = (const float*)d_in[5];
    const float* h0    = (const float*)d_in[6];
    float* out = (float*)d_out;

    cudaFuncSetAttribute(gemm_logits_kernel,
                         cudaFuncAttributeMaxDynamicSharedMemorySize, GEMM_SMEM_BYTES);

    init_kernel<<<1, RNN_NB>>>();
    gather_x_kernel<<<dim3(TSTEPS, HDIM / 256), 256>>>(chars, Wxh, bh);
    rnn_steps_kernel<<<RNN_NB, RNN_THREADS>>>(Whh, h0);
    gemm_logits_kernel<<<(VOCAB + BM - 1) / BM, GEMM_THREADS, GEMM_SMEM_BYTES>>>(Why, by, out);
    softmax_rows_kernel<<<TSTEPS, 1024>>>(out);
}

// round 3
// speedup vs baseline: 1.8159x; 1.8159x over previous
#include <cuda_runtime.h>
#include <math.h>
#include <stdint.h>

#define HDIM   1024
#define TSTEPS 256
#define VOCAB  50257

// ---------------- recurrence config ----------------
#define RNN_NB      32          // blocks; lane i of the poll warp watches block i
#define RNN_THREADS 1024        // 32 warps -> one Whh row per warp
#define FLAG_PAD    128         // 128 uints = 512B between flags -> distinct L2 slices

// -------- device scratch (no allocations allowed) --------
__device__ __align__(16) float g_X[TSTEPS * HDIM];   // Wxh[:, c_t] + bh
__device__ __align__(16) float g_H[TSTEPS * HDIM];   // hidden states h_t
__device__ unsigned g_flags[RNN_NB * FLAG_PAD];      // padded per-block step flags

// ---- memory-model helpers (release/acquire message passing, gpu scope)
__device__ __forceinline__ void fence_acqrel_gpu() {
    asm volatile("fence.acq_rel.gpu;" ::: "memory");
}
__device__ __forceinline__ void st_relaxed_gpu(unsigned* p, unsigned v) {
    asm volatile("st.relaxed.gpu.u32 [%0], %1;" :: "l"(p), "r"(v) : "memory");
}
__device__ __forceinline__ unsigned ld_relaxed_gpu(const unsigned* p) {
    unsigned v;
    asm volatile("ld.relaxed.gpu.u32 %0, [%1];" : "=r"(v) : "l"(p) : "memory");
    return v;
}

// ---------------- init: reset flags every launch (graph-replay determinism)
__global__ void init_kernel() {
    if (threadIdx.x < RNN_NB) g_flags[threadIdx.x * FLAG_PAD] = 0u;
}

// ---------------- gather: g_X[t][h] = Wxh[h][c_t] + bh[h]
__global__ void gather_x_kernel(const int* __restrict__ chars,
                                const float* __restrict__ Wxh,
                                const float* __restrict__ bh) {
    int t = blockIdx.x;
    int h = blockIdx.y * blockDim.x + threadIdx.x;
    int c = chars[t];
    g_X[t * HDIM + h] = Wxh[(size_t)h * VOCAB + c] + bh[h];
}

// ---------------- phase 1: sequential recurrence, 32 persistent blocks.
// One warp owns one Whh row in registers. Grid barrier: padded spread flags,
// ONE polling warp per block (lane i polls block i's flag) -> no hot-line storms.
__global__ void __launch_bounds__(RNN_THREADS, 1)
rnn_steps_kernel(const float* __restrict__ Whh, const float* __restrict__ h0) {
    __shared__ float sh[HDIM];
    const int tid  = threadIdx.x;
    const int wid  = tid >> 5;
    const int lane = tid & 31;
    const int row  = blockIdx.x * 32 + wid;

    // This warp's Whh row in registers: 8 float4 per lane (32 floats/lane).
    float4 w[8];
    const float4* wrow = reinterpret_cast<const float4*>(Whh + (size_t)row * HDIM);
#pragma unroll
    for (int j = 0; j < 8; ++j) w[j] = wrow[j * 32 + lane];

    // stage h0 (one float per thread)
    sh[tid] = h0[tid];
    __syncthreads();

    for (int t = 0; t < TSTEPS; ++t) {
        // h_t[row] = tanh(Whh[row,:] . h_{t-1} + X[t][row])
        float acc = 0.f;
#pragma unroll
        for (int j = 0; j < 8; ++j) {
            float4 hv = reinterpret_cast<const float4*>(sh)[j * 32 + lane];
            acc += w[j].x * hv.x + w[j].y * hv.y + w[j].z * hv.z + w[j].w * hv.w;
        }
#pragma unroll
        for (int o = 16; o > 0; o >>= 1)
            acc += __shfl_down_sync(0xffffffffu, acc, o);

        if (lane == 0)
            g_H[(size_t)t * HDIM + row] = tanhf(acc + g_X[(size_t)t * HDIM + row]);

        if (t + 1 < TSTEPS) {
            // ---- grid barrier: release-arrive, spread-flag poll by warp 0 only
            __syncthreads();                      // all block h-stores issued
            if (wid == 0) {
                const unsigned target = (unsigned)(t + 1);
                if (lane == 0) {
                    fence_acqrel_gpu();           // release own block's h stores
                    st_relaxed_gpu(&g_flags[blockIdx.x * FLAG_PAD], target);
                }
                unsigned v;
                do {
                    v = ld_relaxed_gpu(&g_flags[lane * FLAG_PAD]);
                } while (!__all_sync(0xffffffffu, v >= target));
                fence_acqrel_gpu();               // acquire all blocks' h stores
            }
            __syncthreads();

            // stage h_t for next step (coalesced, 1 float per thread)
            sh[tid] = g_H[(size_t)t * HDIM + tid];
            __syncthreads();
        }
    }
}

// ---------------- phase 2: tensor-core (tf32 mma) GEMM  (unchanged from R2)
// logits[t][v] = sum_k Why[v][k] * H[t][k] + by[v]
// BM=128 (vocab), BN=256 (ALL time steps -> Why streamed once), BK=32.
#define BM 128
#define BN 256
#define BK 32
#define GEMM_THREADS 512
#define APITCH 36
#define BPITCH 36
#define A_FLOATS (BM * APITCH)
#define B_FLOATS (BN * BPITCH)
#define STAGE_FLOATS (A_FLOATS + B_FLOATS)
#define GEMM_SMEM_BYTES (2 * STAGE_FLOATS * 4)

__device__ __forceinline__ void cp16(uint32_t sdst, const void* gsrc) {
    asm volatile("cp.async.cg.shared.global [%0], [%1], 16;\n" :: "r"(sdst), "l"(gsrc));
}
__device__ __forceinline__ void cp_commit() {
    asm volatile("cp.async.commit_group;\n");
}
template <int N>
__device__ __forceinline__ void cp_wait() {
    asm volatile("cp.async.wait_group %0;\n" :: "n"(N));
}

__device__ __forceinline__ void mma_tf32(float d[4], const uint32_t a[4], const uint32_t b[2]) {
    asm volatile(
        "mma.sync.aligned.m16n8k8.row.col.f32.tf32.tf32.f32 "
        "{%0,%1,%2,%3}, {%4,%5,%6,%7}, {%8,%9}, {%0,%1,%2,%3};\n"
        : "+f"(d[0]), "+f"(d[1]), "+f"(d[2]), "+f"(d[3])
        : "r"(a[0]), "r"(a[1]), "r"(a[2]), "r"(a[3]), "r"(b[0]), "r"(b[1]));
}

extern __shared__ float g_smem[];

__global__ void __launch_bounds__(GEMM_THREADS, 1)
gemm_logits_kernel(const float* __restrict__ Why,
                   const float* __restrict__ by,
                   float* __restrict__ out) {
    const int tid  = threadIdx.x;
    const int lane = tid & 31;
    const int wid  = tid >> 5;
    const int wm   = wid & 3;
    const int wn   = wid >> 2;
    const int m0   = blockIdx.x * BM;

    const uint32_t smem_u = (uint32_t)__cvta_generic_to_shared(g_smem);

    auto load_tile = [&](int stage, int k0) {
        uint32_t sa = smem_u + (uint32_t)(stage * STAGE_FLOATS) * 4u;
        uint32_t sb = sa + (uint32_t)A_FLOATS * 4u;
#pragma unroll
        for (int q = 0; q < 2; ++q) {
            int i = tid + q * GEMM_THREADS;
            int row = i >> 3, ch = i & 7;
            int gm = m0 + row; if (gm > VOCAB - 1) gm = VOCAB - 1;
            cp16(sa + (uint32_t)(row * APITCH + ch * 4) * 4u,
                 Why + (size_t)gm * HDIM + k0 + ch * 4);
        }
#pragma unroll
        for (int q = 0; q < 4; ++q) {
            int i = tid + q * GEMM_THREADS;
            int row = i >> 3, ch = i & 7;
            cp16(sb + (uint32_t)(row * BPITCH + ch * 4) * 4u,
                 g_H + (size_t)row * HDIM + k0 + ch * 4);
        }
        cp_commit();
    };

    float acc[2][8][4] = {};

    load_tile(0, 0);

    const int r = lane >> 2;
    const int c = lane & 3;

    for (int kt = 0; kt < HDIM / BK; ++kt) {
        const int cur = kt & 1;
        if (kt + 1 < HDIM / BK) {
            load_tile(cur ^ 1, (kt + 1) * BK);
            cp_wait<1>();
        } else {
            cp_wait<0>();
        }
        __syncthreads();

        const float* As = g_smem + cur * STAGE_FLOATS;
        const float* Bs = As + A_FLOATS;

#pragma unroll
        for (int ki = 0; ki < BK / 8; ++ki) {
            uint32_t a[2][4], b[8][2];
            const int kk = ki * 8 + c;
#pragma unroll
            for (int mi = 0; mi < 2; ++mi) {
                const int mr = wm * 32 + mi * 16 + r;
                a[mi][0] = __float_as_uint(As[(mr    ) * APITCH + kk    ]);
                a[mi][1] = __float_as_uint(As[(mr + 8) * APITCH + kk    ]);
                a[mi][2] = __float_as_uint(As[(mr    ) * APITCH + kk + 4]);
                a[mi][3] = __float_as_uint(As[(mr + 8) * APITCH + kk + 4]);
            }
#pragma unroll
            for (int nf = 0; nf < 8; ++nf) {
                const int nc = wn * 64 + nf * 8 + r;
                b[nf][0] = __float_as_uint(Bs[nc * BPITCH + kk    ]);
                b[nf][1] = __float_as_uint(Bs[nc * BPITCH + kk + 4]);
            }
#pragma unroll
            for (int mi = 0; mi < 2; ++mi)
#pragma unroll
                for (int nf = 0; nf < 8; ++nf)
                    mma_tf32(acc[mi][nf], a[mi], b[nf]);
        }
        __syncthreads();
    }

#pragma unroll
    for (int mi = 0; mi < 2; ++mi) {
        const int v0 = m0 + wm * 32 + mi * 16 + r;
        const int v1 = v0 + 8;
        const float bias0 = (v0 < VOCAB) ? by[v0] : 0.f;
        const float bias1 = (v1 < VOCAB) ? by[v1] : 0.f;
#pragma unroll
        for (int nf = 0; nf < 8; ++nf) {
            const int t0 = wn * 64 + nf * 8 + c * 2;
            const int t1 = t0 + 1;
            if (v0 < VOCAB) {
                out[(size_t)t0 * VOCAB + v0] = acc[mi][nf][0] + bias0;
                out[(size_t)t1 * VOCAB + v0] = acc[mi][nf][1] + bias0;
            }
            if (v1 < VOCAB) {
                out[(size_t)t0 * VOCAB + v1] = acc[mi][nf][2] + bias1;
                out[(size_t)t1 * VOCAB + v1] = acc[mi][nf][3] + bias1;
            }
        }
    }
}

// ---------------- phase 3: in-place stable softmax over each row of 50257
__global__ void __launch_bounds__(1024) softmax_rows_kernel(float* __restrict__ out) {
    __shared__ float red[1024];
    const int t = blockIdx.x;
    float* row = out + (size_t)t * VOCAB;
    const int tid = threadIdx.x;

    float m = -1e30f;
    for (int i = tid; i < VOCAB; i += 1024) m = fmaxf(m, row[i]);
    red[tid] = m; __syncthreads();
    for (int s = 512; s > 0; s >>= 1) {
        if (tid < s) red[tid] = fmaxf(red[tid], red[tid + s]);
        __syncthreads();
    }
    m = red[0];
    __syncthreads();

    float sum = 0.f;
    for (int i = tid; i < VOCAB; i += 1024) sum += expf(row[i] - m);
    red[tid] = sum; __syncthreads();
    for (int s = 512; s > 0; s >>= 1) {
        if (tid < s) red[tid] += red[tid + s];
        __syncthreads();
    }
    float inv = 1.0f / red[0];
    __syncthreads();

    for (int i = tid; i < VOCAB; i += 1024) row[i] = expf(row[i] - m) * inv;
}

// ---------------- launch ----------------
extern "C" void kernel_launch(void* const* d_in, const int* in_sizes, int n_in,
                              void* d_out, int out_size) {
    const int*   chars = (const int*)  d_in[0];
    const float* Wxh   = (const float*)d_in[1];
    const float* Whh   = (const float*)d_in[2];
    const float* Why   = (const float*)d_in[3];
    const float* bh    = (const float*)d_in[4];
    const float* by    = (const float*)d_in[5];
    const float* h0    = (const float*)d_in[6];
    float* out = (float*)d_out;

    cudaFuncSetAttribute(gemm_logits_kernel,
                         cudaFuncAttributeMaxDynamicSharedMemorySize, GEMM_SMEM_BYTES);

    init_kernel<<<1, RNN_NB>>>();
    gather_x_kernel<<<dim3(TSTEPS, HDIM / 256), 256>>>(chars, Wxh, bh);
    rnn_steps_kernel<<<RNN_NB, RNN_THREADS>>>(Whh, h0);
    gemm_logits_kernel<<<(VOCAB + BM - 1) / BM, GEMM_THREADS, GEMM_SMEM_BYTES>>>(Why, by, out);
    softmax_rows_kernel<<<TSTEPS, 1024>>>(out);
}

// round 4
// speedup vs baseline: 2.0991x; 1.1559x over previous
#include <cuda_runtime.h>
#include <math.h>
#include <stdint.h>

#define HDIM   1024
#define TSTEPS 256
#define VOCAB  50257

// ---------------- recurrence config ----------------
#define RNN_NB      128         // persistent blocks (<148 SMs -> co-resident)
#define RNN_THREADS 256         // 8 warps -> one Whh row per warp
#define FLAG_PAD    256         // 256 uints = 1024B apart: bit10 is in the L2 slice hash

// -------- device scratch (no allocations allowed) --------
__device__ __align__(16) float g_X[TSTEPS * HDIM];   // Wxh[:, c_t] + bh
__device__ __align__(16) float g_H[TSTEPS * HDIM];   // hidden states h_t
__device__ unsigned g_flags[RNN_NB * FLAG_PAD];      // padded per-block step flags

// ---- memory-model helpers
__device__ __forceinline__ void fence_acqrel_gpu() {
    asm volatile("fence.acq_rel.gpu;" ::: "memory");
}
__device__ __forceinline__ void st_release_gpu(unsigned* p, unsigned v) {
    asm volatile("st.release.gpu.u32 [%0], %1;" :: "l"(p), "r"(v) : "memory");
}
__device__ __forceinline__ unsigned ld_relaxed_gpu(const unsigned* p) {
    unsigned v;
    asm volatile("ld.relaxed.gpu.u32 %0, [%1];" : "=r"(v) : "l"(p) : "memory");
    return v;
}

// ---------------- init: reset flags every launch (graph-replay determinism)
__global__ void init_kernel() {
    if (threadIdx.x < RNN_NB) g_flags[threadIdx.x * FLAG_PAD] = 0u;
}

// ---------------- gather: g_X[t][h] = Wxh[h][c_t] + bh[h]
__global__ void gather_x_kernel(const int* __restrict__ chars,
                                const float* __restrict__ Wxh,
                                const float* __restrict__ bh) {
    int t = blockIdx.x;
    int h = blockIdx.y * blockDim.x + threadIdx.x;
    int c = chars[t];
    g_X[t * HDIM + h] = Wxh[(size_t)h * VOCAB + c] + bh[h];
}

// ---------------- phase 1: sequential recurrence, 128 persistent blocks.
// One warp owns one Whh row in registers; h_{t-1} read straight from g_H (L2).
// Grid barrier: 1024B-spread per-block flags, release store + 4 polling warps.
__global__ void __launch_bounds__(RNN_THREADS, 1)
rnn_steps_kernel(const float* __restrict__ Whh, const float* __restrict__ h0) {
    const int wid  = threadIdx.x >> 5;
    const int lane = threadIdx.x & 31;
    const int row  = blockIdx.x * 8 + wid;

    // This warp's Whh row in registers: 8 float4 per lane (32 floats/lane).
    float4 w[8];
    const float4* wrow = reinterpret_cast<const float4*>(Whh + (size_t)row * HDIM);
#pragma unroll
    for (int j = 0; j < 8; ++j) w[j] = wrow[j * 32 + lane];

    for (int t = 0; t < TSTEPS; ++t) {
        const float4* hsrc = (t == 0)
            ? reinterpret_cast<const float4*>(h0)
            : reinterpret_cast<const float4*>(g_H + (size_t)(t - 1) * HDIM);

        const float x = g_X[(size_t)t * HDIM + row];   // issue early, off reduce path

        float acc = 0.f;
#pragma unroll
        for (int j = 0; j < 8; ++j) {
            float4 hv = __ldg(hsrc + j * 32 + lane);   // coalesced 128B per j, MLP=8
            acc += w[j].x * hv.x + w[j].y * hv.y + w[j].z * hv.z + w[j].w * hv.w;
        }
#pragma unroll
        for (int o = 16; o > 0; o >>= 1)
            acc += __shfl_down_sync(0xffffffffu, acc, o);

        if (lane == 0)
            g_H[(size_t)t * HDIM + row] = tanhf(acc + x);

        if (t + 1 < TSTEPS) {
            const unsigned target = (unsigned)(t + 1);
            __syncthreads();                      // all 8 warps' h-stores issued
            if (wid == 0 && lane == 0)
                st_release_gpu(&g_flags[blockIdx.x * FLAG_PAD], target);  // cumulative release
            if (wid < 4) {
                // warp w polls flags [w*32 .. w*32+31], one per lane
                const unsigned* fp = &g_flags[(wid * 32 + lane) * FLAG_PAD];
                unsigned v;
                do { v = ld_relaxed_gpu(fp); } while (!__all_sync(0xffffffffu, v >= target));
                fence_acqrel_gpu();               // acquire all blocks' h stores
            }
            __syncthreads();
        }
    }
}

// ---------------- phase 2: tensor-core (tf32 mma) GEMM  (unchanged)
// logits[t][v] = sum_k Why[v][k] * H[t][k] + by[v]
#define BM 128
#define BN 256
#define BK 32
#define GEMM_THREADS 512
#define APITCH 36
#define BPITCH 36
#define A_FLOATS (BM * APITCH)
#define B_FLOATS (BN * BPITCH)
#define STAGE_FLOATS (A_FLOATS + B_FLOATS)
#define GEMM_SMEM_BYTES (2 * STAGE_FLOATS * 4)

__device__ __forceinline__ void cp16(uint32_t sdst, const void* gsrc) {
    asm volatile("cp.async.cg.shared.global [%0], [%1], 16;\n" :: "r"(sdst), "l"(gsrc));
}
__device__ __forceinline__ void cp_commit() {
    asm volatile("cp.async.commit_group;\n");
}
template <int N>
__device__ __forceinline__ void cp_wait() {
    asm volatile("cp.async.wait_group %0;\n" :: "n"(N));
}

__device__ __forceinline__ void mma_tf32(float d[4], const uint32_t a[4], const uint32_t b[2]) {
    asm volatile(
        "mma.sync.aligned.m16n8k8.row.col.f32.tf32.tf32.f32 "
        "{%0,%1,%2,%3}, {%4,%5,%6,%7}, {%8,%9}, {%0,%1,%2,%3};\n"
        : "+f"(d[0]), "+f"(d[1]), "+f"(d[2]), "+f"(d[3])
        : "r"(a[0]), "r"(a[1]), "r"(a[2]), "r"(a[3]), "r"(b[0]), "r"(b[1]));
}

extern __shared__ float g_smem[];

__global__ void __launch_bounds__(GEMM_THREADS, 1)
gemm_logits_kernel(const float* __restrict__ Why,
                   const float* __restrict__ by,
                   float* __restrict__ out) {
    const int tid  = threadIdx.x;
    const int lane = tid & 31;
    const int wid  = tid >> 5;
    const int wm   = wid & 3;
    const int wn   = wid >> 2;
    const int m0   = blockIdx.x * BM;

    const uint32_t smem_u = (uint32_t)__cvta_generic_to_shared(g_smem);

    auto load_tile = [&](int stage, int k0) {
        uint32_t sa = smem_u + (uint32_t)(stage * STAGE_FLOATS) * 4u;
        uint32_t sb = sa + (uint32_t)A_FLOATS * 4u;
#pragma unroll
        for (int q = 0; q < 2; ++q) {
            int i = tid + q * GEMM_THREADS;
            int row = i >> 3, ch = i & 7;
            int gm = m0 + row; if (gm > VOCAB - 1) gm = VOCAB - 1;
            cp16(sa + (uint32_t)(row * APITCH + ch * 4) * 4u,
                 Why + (size_t)gm * HDIM + k0 + ch * 4);
        }
#pragma unroll
        for (int q = 0; q < 4; ++q) {
            int i = tid + q * GEMM_THREADS;
            int row = i >> 3, ch = i & 7;
            cp16(sb + (uint32_t)(row * BPITCH + ch * 4) * 4u,
                 g_H + (size_t)row * HDIM + k0 + ch * 4);
        }
        cp_commit();
    };

    float acc[2][8][4] = {};

    load_tile(0, 0);

    const int r = lane >> 2;
    const int c = lane & 3;

    for (int kt = 0; kt < HDIM / BK; ++kt) {
        const int cur = kt & 1;
        if (kt + 1 < HDIM / BK) {
            load_tile(cur ^ 1, (kt + 1) * BK);
            cp_wait<1>();
        } else {
            cp_wait<0>();
        }
        __syncthreads();

        const float* As = g_smem + cur * STAGE_FLOATS;
        const float* Bs = As + A_FLOATS;

#pragma unroll
        for (int ki = 0; ki < BK / 8; ++ki) {
            uint32_t a[2][4], b[8][2];
            const int kk = ki * 8 + c;
#pragma unroll
            for (int mi = 0; mi < 2; ++mi) {
                const int mr = wm * 32 + mi * 16 + r;
                a[mi][0] = __float_as_uint(As[(mr    ) * APITCH + kk    ]);
                a[mi][1] = __float_as_uint(As[(mr + 8) * APITCH + kk    ]);
                a[mi][2] = __float_as_uint(As[(mr    ) * APITCH + kk + 4]);
                a[mi][3] = __float_as_uint(As[(mr + 8) * APITCH + kk + 4]);
            }
#pragma unroll
            for (int nf = 0; nf < 8; ++nf) {
                const int nc = wn * 64 + nf * 8 + r;
                b[nf][0] = __float_as_uint(Bs[nc * BPITCH + kk    ]);
                b[nf][1] = __float_as_uint(Bs[nc * BPITCH + kk + 4]);
            }
#pragma unroll
            for (int mi = 0; mi < 2; ++mi)
#pragma unroll
                for (int nf = 0; nf < 8; ++nf)
                    mma_tf32(acc[mi][nf], a[mi], b[nf]);
        }
        __syncthreads();
    }

#pragma unroll
    for (int mi = 0; mi < 2; ++mi) {
        const int v0 = m0 + wm * 32 + mi * 16 + r;
        const int v1 = v0 + 8;
        const float bias0 = (v0 < VOCAB) ? by[v0] : 0.f;
        const float bias1 = (v1 < VOCAB) ? by[v1] : 0.f;
#pragma unroll
        for (int nf = 0; nf < 8; ++nf) {
            const int t0 = wn * 64 + nf * 8 + c * 2;
            const int t1 = t0 + 1;
            if (v0 < VOCAB) {
                out[(size_t)t0 * VOCAB + v0] = acc[mi][nf][0] + bias0;
                out[(size_t)t1 * VOCAB + v0] = acc[mi][nf][1] + bias0;
            }
            if (v1 < VOCAB) {
                out[(size_t)t0 * VOCAB + v1] = acc[mi][nf][2] + bias1;
                out[(size_t)t1 * VOCAB + v1] = acc[mi][nf][3] + bias1;
            }
        }
    }
}

// ---------------- phase 3: in-place stable softmax over each row of 50257
__global__ void __launch_bounds__(1024) softmax_rows_kernel(float* __restrict__ out) {
    __shared__ float red[1024];
    const int t = blockIdx.x;
    float* row = out + (size_t)t * VOCAB;
    const int tid = threadIdx.x;

    float m = -1e30f;
    for (int i = tid; i < VOCAB; i += 1024) m = fmaxf(m, row[i]);
    red[tid] = m; __syncthreads();
    for (int s = 512; s > 0; s >>= 1) {
        if (tid < s) red[tid] = fmaxf(red[tid], red[tid + s]);
        __syncthreads();
    }
    m = red[0];
    __syncthreads();

    float sum = 0.f;
    for (int i = tid; i < VOCAB; i += 1024) sum += expf(row[i] - m);
    red[tid] = sum; __syncthreads();
    for (int s = 512; s > 0; s >>= 1) {
        if (tid < s) red[tid] += red[tid + s];
        __syncthreads();
    }
    float inv = 1.0f / red[0];
    __syncthreads();

    for (int i = tid; i < VOCAB; i += 1024) row[i] = expf(row[i] - m) * inv;
}

// ---------------- launch ----------------
extern "C" void kernel_launch(void* const* d_in, const int* in_sizes, int n_in,
                              void* d_out, int out_size) {
    const int*   chars = (const int*)  d_in[0];
    const float* Wxh   = (const float*)d_in[1];
    const float* Whh   = (const float*)d_in[2];
    const float* Why   = (const float*)d_in[3];
    const float* bh    = (const float*)d_in[4];
    const float* by    = (const float*)d_in[5];
    const float* h0    = (const float*)d_in[6];
    float* out = (float*)d_out;

    cudaFuncSetAttribute(gemm_logits_kernel,
                         cudaFuncAttributeMaxDynamicSharedMemorySize, GEMM_SMEM_BYTES);

    init_kernel<<<1, RNN_NB>>>();
    gather_x_kernel<<<dim3(TSTEPS, HDIM / 256), 256>>>(chars, Wxh, bh);
    rnn_steps_kernel<<<RNN_NB, RNN_THREADS>>>(Whh, h0);
    gemm_logits_kernel<<<(VOCAB + BM - 1) / BM, GEMM_THREADS, GEMM_SMEM_BYTES>>>(Why, by, out);
    softmax_rows_kernel<<<TSTEPS, 1024>>>(out);
}

// round 5
// speedup vs baseline: 2.8937x; 1.3785x over previous
#include <cuda_runtime.h>
#include <math.h>
#include <stdint.h>

#define HDIM   1024
#define TSTEPS 256
#define VOCAB  50257

// ---------------- recurrence config ----------------
#define RNN_NB      64          // persistent blocks
#define RNN_THREADS 256         // 8 warps, 2 rows per warp -> 16 rows per block
#define VEC_PER_BLK 6           // 16 h values -> 6 vectors of (3h + tag)
#define NVEC        (RNN_NB * VEC_PER_BLK)   // 384
#define VEC_STRIDE  8           // float4 units: 8*16B = 128B -> one L2 line per vector

// -------- device scratch (no allocations allowed) --------
__device__ __align__(16)  float g_X[TSTEPS * HDIM];       // Wxh[:, c_t] + bh
__device__ __align__(16)  float g_H[TSTEPS * HDIM];       // hidden states h_t
__device__ __align__(128) float4 g_pub[2 * NVEC * VEC_STRIDE];  // tagged h exchange (96KB)

// ---- volatile 16B ld/st: single 128-bit transaction, tag+data atomic together
__device__ __forceinline__ float4 ldv4(const float4* p) {
    float4 v;
    asm volatile("ld.volatile.global.v4.f32 {%0,%1,%2,%3}, [%4];"
                 : "=f"(v.x), "=f"(v.y), "=f"(v.z), "=f"(v.w) : "l"(p));
    return v;
}
__device__ __forceinline__ void stv4(float4* p, float4 v) {
    asm volatile("st.volatile.global.v4.f32 [%0], {%1,%2,%3,%4};"
                 :: "l"(p), "f"(v.x), "f"(v.y), "f"(v.z), "f"(v.w) : "memory");
}

// ---------------- init: clear exchange tags each launch (graph-replay determinism)
__global__ void init_kernel() {
    int i = blockIdx.x * blockDim.x + threadIdx.x;
    if (i < 2 * NVEC) g_pub[i * VEC_STRIDE].w = 0.0f;   // tag = int 0
}

// ---------------- gather: g_X[t][h] = Wxh[h][c_t] + bh[h]
__global__ void gather_x_kernel(const int* __restrict__ chars,
                                const float* __restrict__ Wxh,
                                const float* __restrict__ bh) {
    int t = blockIdx.x;
    int h = blockIdx.y * blockDim.x + threadIdx.x;
    int c = chars[t];
    g_X[t * HDIM + h] = Wxh[(size_t)h * VOCAB + c] + bh[h];
}

// ---------------- phase 1: sequential recurrence, fence-free tagged exchange.
// 64 blocks x 8 warps; each warp owns TWO Whh rows in registers.
// Publication: 6x 16B vectors (3 h + step tag) per block, one per 128B line.
__global__ void __launch_bounds__(RNN_THREADS, 1)
rnn_steps_kernel(const float* __restrict__ Whh, const float* __restrict__ h0) {
    __shared__ float sh[HDIM];     // h_{t-1}, assembled from polled vectors
    __shared__ float hout[16];     // this block's 16 new h values

    const int tid  = threadIdx.x;
    const int wid  = tid >> 5;
    const int lane = tid & 31;
    const int r0   = blockIdx.x * 16 + wid * 2;    // this warp's two rows
    const int r1   = r0 + 1;

    // Whh rows in registers: 2 rows x 8 float4 per lane.
    float4 w0[8], w1[8];
    {
        const float4* p0 = reinterpret_cast<const float4*>(Whh + (size_t)r0 * HDIM);
        const float4* p1 = reinterpret_cast<const float4*>(Whh + (size_t)r1 * HDIM);
#pragma unroll
        for (int j = 0; j < 8; ++j) { w0[j] = p0[j * 32 + lane]; w1[j] = p1[j * 32 + lane]; }
    }

    // stage h0 into smem
    reinterpret_cast<float4*>(sh)[tid] = reinterpret_cast<const float4*>(h0)[tid];
    __syncthreads();

    for (int t = 0; t < TSTEPS; ++t) {
        // prefetch x for this warp's rows (lane 0), off the critical reduce path
        float x0 = 0.f, x1 = 0.f;
        if (lane == 0) {
            x0 = g_X[(size_t)t * HDIM + r0];
            x1 = g_X[(size_t)t * HDIM + r1];
        }

        float a0 = 0.f, a1 = 0.f;
#pragma unroll
        for (int j = 0; j < 8; ++j) {
            float4 hv = reinterpret_cast<const float4*>(sh)[j * 32 + lane];
            a0 += w0[j].x * hv.x + w0[j].y * hv.y + w0[j].z * hv.z + w0[j].w * hv.w;
            a1 += w1[j].x * hv.x + w1[j].y * hv.y + w1[j].z * hv.z + w1[j].w * hv.w;
        }
#pragma unroll
        for (int o = 16; o > 0; o >>= 1) {
            a0 += __shfl_down_sync(0xffffffffu, a0, o);
            a1 += __shfl_down_sync(0xffffffffu, a1, o);
        }

        if (lane == 0) {
            float h0v = tanhf(a0 + x0);
            float h1v = tanhf(a1 + x1);
            g_H[(size_t)t * HDIM + r0] = h0v;
            g_H[(size_t)t * HDIM + r1] = h1v;
            hout[wid * 2]     = h0v;
            hout[wid * 2 + 1] = h1v;
        }

        if (t + 1 < TSTEPS) {
            const int tag = t + 1;
            __syncthreads();   // hout complete; everyone done reading sh

            // publish: 6 tagged vectors, parity-selected buffer
            if (tid < VEC_PER_BLK) {
                const int j = tid;
                float4 v;
                v.x = hout[3 * j];
                v.y = hout[(3 * j + 1 < 16) ? 3 * j + 1 : 15];
                v.z = hout[(3 * j + 2 < 16) ? 3 * j + 2 : 15];
                v.w = __int_as_float(tag);
                stv4(&g_pub[((t & 1) * NVEC + blockIdx.x * VEC_PER_BLK + j) * VEC_STRIDE], v);
            }

            // poll ALL blocks' vectors; tag match => payload is from this step
            const float4* base = &g_pub[(t & 1) * NVEC * VEC_STRIDE];
            {
                int g = tid;
                float4 v;
                do { v = ldv4(base + g * VEC_STRIDE); } while (__float_as_int(v.w) != tag);
                int b = g / VEC_PER_BLK, j = g % VEC_PER_BLK, bs = b * 16, jj = 3 * j;
                sh[bs + jj] = v.x;
                sh[bs + ((jj + 1 < 16) ? jj + 1 : 15)] = v.y;
                sh[bs + ((jj + 2 < 16) ? jj + 2 : 15)] = v.z;
            }
            if (tid < NVEC - RNN_THREADS) {
                int g = tid + RNN_THREADS;
                float4 v;
                do { v = ldv4(base + g * VEC_STRIDE); } while (__float_as_int(v.w) != tag);
                int b = g / VEC_PER_BLK, j = g % VEC_PER_BLK, bs = b * 16, jj = 3 * j;
                sh[bs + jj] = v.x;
                sh[bs + ((jj + 1 < 16) ? jj + 1 : 15)] = v.y;
                sh[bs + ((jj + 2 < 16) ? jj + 2 : 15)] = v.z;
            }
            __syncthreads();   // sh = h_t complete
        }
    }
}

// ---------------- phase 2: tensor-core (tf32 mma) GEMM  (unchanged)
#define BM 128
#define BN 256
#define BK 32
#define GEMM_THREADS 512
#define APITCH 36
#define BPITCH 36
#define A_FLOATS (BM * APITCH)
#define B_FLOATS (BN * BPITCH)
#define STAGE_FLOATS (A_FLOATS + B_FLOATS)
#define GEMM_SMEM_BYTES (2 * STAGE_FLOATS * 4)

__device__ __forceinline__ void cp16(uint32_t sdst, const void* gsrc) {
    asm volatile("cp.async.cg.shared.global [%0], [%1], 16;\n" :: "r"(sdst), "l"(gsrc));
}
__device__ __forceinline__ void cp_commit() {
    asm volatile("cp.async.commit_group;\n");
}
template <int N>
__device__ __forceinline__ void cp_wait() {
    asm volatile("cp.async.wait_group %0;\n" :: "n"(N));
}

__device__ __forceinline__ void mma_tf32(float d[4], const uint32_t a[4], const uint32_t b[2]) {
    asm volatile(
        "mma.sync.aligned.m16n8k8.row.col.f32.tf32.tf32.f32 "
        "{%0,%1,%2,%3}, {%4,%5,%6,%7}, {%8,%9}, {%0,%1,%2,%3};\n"
        : "+f"(d[0]), "+f"(d[1]), "+f"(d[2]), "+f"(d[3])
        : "r"(a[0]), "r"(a[1]), "r"(a[2]), "r"(a[3]), "r"(b[0]), "r"(b[1]));
}

extern __shared__ float g_smem[];

__global__ void __launch_bounds__(GEMM_THREADS, 1)
gemm_logits_kernel(const float* __restrict__ Why,
                   const float* __restrict__ by,
                   float* __restrict__ out) {
    const int tid  = threadIdx.x;
    const int lane = tid & 31;
    const int wid  = tid >> 5;
    const int wm   = wid & 3;
    const int wn   = wid >> 2;
    const int m0   = blockIdx.x * BM;

    const uint32_t smem_u = (uint32_t)__cvta_generic_to_shared(g_smem);

    auto load_tile = [&](int stage, int k0) {
        uint32_t sa = smem_u + (uint32_t)(stage * STAGE_FLOATS) * 4u;
        uint32_t sb = sa + (uint32_t)A_FLOATS * 4u;
#pragma unroll
        for (int q = 0; q < 2; ++q) {
            int i = tid + q * GEMM_THREADS;
            int row = i >> 3, ch = i & 7;
            int gm = m0 + row; if (gm > VOCAB - 1) gm = VOCAB - 1;
            cp16(sa + (uint32_t)(row * APITCH + ch * 4) * 4u,
                 Why + (size_t)gm * HDIM + k0 + ch * 4);
        }
#pragma unroll
        for (int q = 0; q < 4; ++q) {
            int i = tid + q * GEMM_THREADS;
            int row = i >> 3, ch = i & 7;
            cp16(sb + (uint32_t)(row * BPITCH + ch * 4) * 4u,
                 g_H + (size_t)row * HDIM + k0 + ch * 4);
        }
        cp_commit();
    };

    float acc[2][8][4] = {};

    load_tile(0, 0);

    const int r = lane >> 2;
    const int c = lane & 3;

    for (int kt = 0; kt < HDIM / BK; ++kt) {
        const int cur = kt & 1;
        if (kt + 1 < HDIM / BK) {
            load_tile(cur ^ 1, (kt + 1) * BK);
            cp_wait<1>();
        } else {
            cp_wait<0>();
        }
        __syncthreads();

        const float* As = g_smem + cur * STAGE_FLOATS;
        const float* Bs = As + A_FLOATS;

#pragma unroll
        for (int ki = 0; ki < BK / 8; ++ki) {
            uint32_t a[2][4], b[8][2];
            const int kk = ki * 8 + c;
#pragma unroll
            for (int mi = 0; mi < 2; ++mi) {
                const int mr = wm * 32 + mi * 16 + r;
                a[mi][0] = __float_as_uint(As[(mr    ) * APITCH + kk    ]);
                a[mi][1] = __float_as_uint(As[(mr + 8) * APITCH + kk    ]);
                a[mi][2] = __float_as_uint(As[(mr    ) * APITCH + kk + 4]);
                a[mi][3] = __float_as_uint(As[(mr + 8) * APITCH + kk + 4]);
            }
#pragma unroll
            for (int nf = 0; nf < 8; ++nf) {
                const int nc = wn * 64 + nf * 8 + r;
                b[nf][0] = __float_as_uint(Bs[nc * BPITCH + kk    ]);
                b[nf][1] = __float_as_uint(Bs[nc * BPITCH + kk + 4]);
            }
#pragma unroll
            for (int mi = 0; mi < 2; ++mi)
#pragma unroll
                for (int nf = 0; nf < 8; ++nf)
                    mma_tf32(acc[mi][nf], a[mi], b[nf]);
        }
        __syncthreads();
    }

#pragma unroll
    for (int mi = 0; mi < 2; ++mi) {
        const int v0 = m0 + wm * 32 + mi * 16 + r;
        const int v1 = v0 + 8;
        const float bias0 = (v0 < VOCAB) ? by[v0] : 0.f;
        const float bias1 = (v1 < VOCAB) ? by[v1] : 0.f;
#pragma unroll
        for (int nf = 0; nf < 8; ++nf) {
            const int t0 = wn * 64 + nf * 8 + c * 2;
            const int t1 = t0 + 1;
            if (v0 < VOCAB) {
                out[(size_t)t0 * VOCAB + v0] = acc[mi][nf][0] + bias0;
                out[(size_t)t1 * VOCAB + v0] = acc[mi][nf][1] + bias0;
            }
            if (v1 < VOCAB) {
                out[(size_t)t0 * VOCAB + v1] = acc[mi][nf][2] + bias1;
                out[(size_t)t1 * VOCAB + v1] = acc[mi][nf][3] + bias1;
            }
        }
    }
}

// ---------------- phase 3: in-place stable softmax over each row of 50257
__global__ void __launch_bounds__(1024) softmax_rows_kernel(float* __restrict__ out) {
    __shared__ float red[1024];
    const int t = blockIdx.x;
    float* row = out + (size_t)t * VOCAB;
    const int tid = threadIdx.x;

    float m = -1e30f;
    for (int i = tid; i < VOCAB; i += 1024) m = fmaxf(m, row[i]);
    red[tid] = m; __syncthreads();
    for (int s = 512; s > 0; s >>= 1) {
        if (tid < s) red[tid] = fmaxf(red[tid], red[tid + s]);
        __syncthreads();
    }
    m = red[0];
    __syncthreads();

    float sum = 0.f;
    for (int i = tid; i < VOCAB; i += 1024) sum += expf(row[i] - m);
    red[tid] = sum; __syncthreads();
    for (int s = 512; s > 0; s >>= 1) {
        if (tid < s) red[tid] += red[tid + s];
        __syncthreads();
    }
    float inv = 1.0f / red[0];
    __syncthreads();

    for (int i = tid; i < VOCAB; i += 1024) row[i] = expf(row[i] - m) * inv;
}

// ---------------- launch ----------------
extern "C" void kernel_launch(void* const* d_in, const int* in_sizes, int n_in,
                              void* d_out, int out_size) {
    const int*   chars = (const int*)  d_in[0];
    const float* Wxh   = (const float*)d_in[1];
    const float* Whh   = (const float*)d_in[2];
    const float* Why   = (const float*)d_in[3];
    const float* bh    = (const float*)d_in[4];
    const float* by    = (const float*)d_in[5];
    const float* h0    = (const float*)d_in[6];
    float* out = (float*)d_out;

    cudaFuncSetAttribute(gemm_logits_kernel,
                         cudaFuncAttributeMaxDynamicSharedMemorySize, GEMM_SMEM_BYTES);

    init_kernel<<<1, 1024>>>();
    gather_x_kernel<<<dim3(TSTEPS, HDIM / 256), 256>>>(chars, Wxh, bh);
    rnn_steps_kernel<<<RNN_NB, RNN_THREADS>>>(Whh, h0);
    gemm_logits_kernel<<<(VOCAB + BM - 1) / BM, GEMM_THREADS, GEMM_SMEM_BYTES>>>(Why, by, out);
    softmax_rows_kernel<<<TSTEPS, 1024>>>(out);
}

// round 6
// speedup vs baseline: 3.1699x; 1.0955x over previous
#include <cuda_runtime.h>
#include <cuda_bf16.h>
#include <math.h>
#include <stdint.h>

#define HDIM   1024
#define TSTEPS 256
#define VOCAB  50257

// ---------------- recurrence config (unchanged from R5 WIN) ----------------
#define RNN_NB      64
#define RNN_THREADS 256
#define VEC_PER_BLK 6
#define NVEC        (RNN_NB * VEC_PER_BLK)   // 384
#define VEC_STRIDE  8                        // 128B per vector -> own L2 line

// -------- device scratch (no allocations allowed) --------
__device__ __align__(16)  float g_X[TSTEPS * HDIM];            // Wxh[:, c_t] + bh
__device__ __align__(16)  __nv_bfloat16 g_Hb[TSTEPS * HDIM];   // hidden states (bf16, GEMM B input)
__device__ __align__(128) float4 g_pub[2 * NVEC * VEC_STRIDE]; // tagged h exchange

// ---- volatile 16B ld/st: single 128-bit transaction, tag+data atomic together
__device__ __forceinline__ float4 ldv4(const float4* p) {
    float4 v;
    asm volatile("ld.volatile.global.v4.f32 {%0,%1,%2,%3}, [%4];"
                 : "=f"(v.x), "=f"(v.y), "=f"(v.z), "=f"(v.w) : "l"(p));
    return v;
}
__device__ __forceinline__ void stv4(float4* p, float4 v) {
    asm volatile("st.volatile.global.v4.f32 [%0], {%1,%2,%3,%4};"
                 :: "l"(p), "f"(v.x), "f"(v.y), "f"(v.z), "f"(v.w) : "memory");
}

// ---------------- init: clear exchange tags each launch
__global__ void init_kernel() {
    int i = blockIdx.x * blockDim.x + threadIdx.x;
    if (i < 2 * NVEC) g_pub[i * VEC_STRIDE].w = 0.0f;
}

// ---------------- gather: g_X[t][h] = Wxh[h][c_t] + bh[h]
__global__ void gather_x_kernel(const int* __restrict__ chars,
                                const float* __restrict__ Wxh,
                                const float* __restrict__ bh) {
    int t = blockIdx.x;
    int h = blockIdx.y * blockDim.x + threadIdx.x;
    int c = chars[t];
    g_X[t * HDIM + h] = Wxh[(size_t)h * VOCAB + c] + bh[h];
}

// ---------------- phase 1: recurrence with fence-free tagged exchange (R5 design).
// Only change: h_t stored to g_Hb as bf16 (g_H had no other consumer than GEMM).
__global__ void __launch_bounds__(RNN_THREADS, 1)
rnn_steps_kernel(const float* __restrict__ Whh, const float* __restrict__ h0) {
    __shared__ float sh[HDIM];
    __shared__ float hout[16];

    const int tid  = threadIdx.x;
    const int wid  = tid >> 5;
    const int lane = tid & 31;
    const int r0   = blockIdx.x * 16 + wid * 2;
    const int r1   = r0 + 1;

    float4 w0[8], w1[8];
    {
        const float4* p0 = reinterpret_cast<const float4*>(Whh + (size_t)r0 * HDIM);
        const float4* p1 = reinterpret_cast<const float4*>(Whh + (size_t)r1 * HDIM);
#pragma unroll
        for (int j = 0; j < 8; ++j) { w0[j] = p0[j * 32 + lane]; w1[j] = p1[j * 32 + lane]; }
    }

    reinterpret_cast<float4*>(sh)[tid] = reinterpret_cast<const float4*>(h0)[tid];
    __syncthreads();

    for (int t = 0; t < TSTEPS; ++t) {
        float x0 = 0.f, x1 = 0.f;
        if (lane == 0) {
            x0 = g_X[(size_t)t * HDIM + r0];
            x1 = g_X[(size_t)t * HDIM + r1];
        }

        float a0 = 0.f, a1 = 0.f;
#pragma unroll
        for (int j = 0; j < 8; ++j) {
            float4 hv = reinterpret_cast<const float4*>(sh)[j * 32 + lane];
            a0 += w0[j].x * hv.x + w0[j].y * hv.y + w0[j].z * hv.z + w0[j].w * hv.w;
            a1 += w1[j].x * hv.x + w1[j].y * hv.y + w1[j].z * hv.z + w1[j].w * hv.w;
        }
#pragma unroll
        for (int o = 16; o > 0; o >>= 1) {
            a0 += __shfl_down_sync(0xffffffffu, a0, o);
            a1 += __shfl_down_sync(0xffffffffu, a1, o);
        }

        if (lane == 0) {
            float h0v = tanhf(a0 + x0);
            float h1v = tanhf(a1 + x1);
            g_Hb[(size_t)t * HDIM + r0] = __float2bfloat16(h0v);
            g_Hb[(size_t)t * HDIM + r1] = __float2bfloat16(h1v);
            hout[wid * 2]     = h0v;
            hout[wid * 2 + 1] = h1v;
        }

        if (t + 1 < TSTEPS) {
            const int tag = t + 1;
            __syncthreads();

            if (tid < VEC_PER_BLK) {
                const int j = tid;
                float4 v;
                v.x = hout[3 * j];
                v.y = hout[(3 * j + 1 < 16) ? 3 * j + 1 : 15];
                v.z = hout[(3 * j + 2 < 16) ? 3 * j + 2 : 15];
                v.w = __int_as_float(tag);
                stv4(&g_pub[((t & 1) * NVEC + blockIdx.x * VEC_PER_BLK + j) * VEC_STRIDE], v);
            }

            const float4* base = &g_pub[(t & 1) * NVEC * VEC_STRIDE];
            {
                int g = tid;
                float4 v;
                do { v = ldv4(base + g * VEC_STRIDE); } while (__float_as_int(v.w) != tag);
                int b = g / VEC_PER_BLK, j = g % VEC_PER_BLK, bs = b * 16, jj = 3 * j;
                sh[bs + jj] = v.x;
                sh[bs + ((jj + 1 < 16) ? jj + 1 : 15)] = v.y;
                sh[bs + ((jj + 2 < 16) ? jj + 2 : 15)] = v.z;
            }
            if (tid < NVEC - RNN_THREADS) {
                int g = tid + RNN_THREADS;
                float4 v;
                do { v = ldv4(base + g * VEC_STRIDE); } while (__float_as_int(v.w) != tag);
                int b = g / VEC_PER_BLK, j = g % VEC_PER_BLK, bs = b * 16, jj = 3 * j;
                sh[bs + jj] = v.x;
                sh[bs + ((jj + 1 < 16) ? jj + 1 : 15)] = v.y;
                sh[bs + ((jj + 2 < 16) ? jj + 2 : 15)] = v.z;
            }
            __syncthreads();
        }
    }
}

// ---------------- phase 2: bf16 tensor-core GEMM (m16n8k16)
// logits[t][v] = sum_k Why[v][k] * H[t][k] + by[v]
// A (Why) converted fp32->bf16 in-kernel via LDG+cvt+STS; B (g_Hb) cp.async bf16.
#define BM 128
#define BN 256
#define BK 32
#define GEMM_THREADS 512
#define PITCH_H 40                            // bf16 elems per smem row: conflict-free + 16B-aligned
#define A_TILE_H (BM * PITCH_H)               // 5120 bf16
#define B_TILE_H (BN * PITCH_H)               // 10240 bf16
#define STAGE_H  (A_TILE_H + B_TILE_H)        // 15360 bf16 = 30720 B
#define GEMM_SMEM_BYTES (2 * STAGE_H * 2)     // 61440 B

__device__ __forceinline__ void cp16(uint32_t sdst, const void* gsrc) {
    asm volatile("cp.async.cg.shared.global [%0], [%1], 16;\n" :: "r"(sdst), "l"(gsrc));
}
__device__ __forceinline__ void cp_commit() {
    asm volatile("cp.async.commit_group;\n");
}
__device__ __forceinline__ void cp_wait0() {
    asm volatile("cp.async.wait_group 0;\n");
}

__device__ __forceinline__ uint32_t pack_bf16(float lo, float hi) {
    __nv_bfloat162 v = __floats2bfloat162_rn(lo, hi);
    return *reinterpret_cast<uint32_t*>(&v);
}

__device__ __forceinline__ void mma_bf16(float d[4], const uint32_t a[4], const uint32_t b[2]) {
    asm volatile(
        "mma.sync.aligned.m16n8k16.row.col.f32.bf16.bf16.f32 "
        "{%0,%1,%2,%3}, {%4,%5,%6,%7}, {%8,%9}, {%0,%1,%2,%3};\n"
        : "+f"(d[0]), "+f"(d[1]), "+f"(d[2]), "+f"(d[3])
        : "r"(a[0]), "r"(a[1]), "r"(a[2]), "r"(a[3]), "r"(b[0]), "r"(b[1]));
}

extern __shared__ __nv_bfloat16 g_smem[];

__global__ void __launch_bounds__(GEMM_THREADS, 1)
gemm_logits_kernel(const float* __restrict__ Why,
                   const float* __restrict__ by,
                   float* __restrict__ out) {
    const int tid  = threadIdx.x;
    const int lane = tid & 31;
    const int wid  = tid >> 5;
    const int wm   = wid & 3;        // warp m (0..3) -> 32 vocab rows
    const int wn   = wid >> 2;       // warp n (0..3) -> 64 time cols
    const int m0   = blockIdx.x * BM;

    const uint32_t smem_u = (uint32_t)__cvta_generic_to_shared(g_smem);

    // --- A (Why) LDG address: thread -> (row, k0); 8 fp32 per thread per kt
    const int arow = tid >> 2;            // 0..127
    const int ak0  = (tid & 3) * 8;       // 0,8,16,24
    int agm = m0 + arow; if (agm > VOCAB - 1) agm = VOCAB - 1;
    const float4* Aptr = reinterpret_cast<const float4*>(Why + (size_t)agm * HDIM + ak0);

    // --- B loader: 256 rows x 4 chunks of 16B = 1024 -> 2 per thread
    auto load_B = [&](int stage, int k0) {
        uint32_t sb = smem_u + (uint32_t)(stage * STAGE_H + A_TILE_H) * 2u;
#pragma unroll
        for (int q = 0; q < 2; ++q) {
            int i = tid + q * GEMM_THREADS;
            int row = i >> 2, ch = i & 3;
            cp16(sb + (uint32_t)(row * PITCH_H + ch * 8) * 2u,
                 g_Hb + (size_t)row * HDIM + k0 + ch * 8);
        }
        cp_commit();
    };

    float acc[2][8][4] = {};

    // prologue: A regs for kt=0, B cp.async for kt=0
    float4 fa = Aptr[0];
    float4 fb = Aptr[1];
    load_B(0, 0);

    const int r = lane >> 2;   // group id
    const int c = lane & 3;    // thread-in-group

    for (int kt = 0; kt < HDIM / BK; ++kt) {
        const int cur = kt & 1;
        __nv_bfloat16* As = g_smem + cur * STAGE_H;
        const __nv_bfloat16* Bs = As + A_TILE_H;

        // convert & store this kt's A regs into smem (one STS.128)
        {
            uint4 p;
            p.x = pack_bf16(fa.x, fa.y);
            p.y = pack_bf16(fa.z, fa.w);
            p.z = pack_bf16(fb.x, fb.y);
            p.w = pack_bf16(fb.z, fb.w);
            *reinterpret_cast<uint4*>(As + arow * PITCH_H + ak0) = p;
        }
        cp_wait0();          // B(cur) resident
        __syncthreads();     // A(cur) + B(cur) visible to all

        // issue next tile's loads (overlap with mma below)
        if (kt + 1 < HDIM / BK) {
            const float4* An = Aptr + (kt + 1) * (BK / 4);
            fa = An[0];
            fb = An[1];
            load_B(cur ^ 1, (kt + 1) * BK);
        }

        // mma: 2 ki of k=16
#pragma unroll
        for (int ki = 0; ki < 2; ++ki) {
            uint32_t a[2][4], b[8][2];
            const int kk = ki * 16 + 2 * c;   // bf16 element index in row
#pragma unroll
            for (int mi = 0; mi < 2; ++mi) {
                const int mr = wm * 32 + mi * 16 + r;
                a[mi][0] = *reinterpret_cast<const uint32_t*>(As + (mr    ) * PITCH_H + kk    );
                a[mi][1] = *reinterpret_cast<const uint32_t*>(As + (mr + 8) * PITCH_H + kk    );
                a[mi][2] = *reinterpret_cast<const uint32_t*>(As + (mr    ) * PITCH_H + kk + 8);
                a[mi][3] = *reinterpret_cast<const uint32_t*>(As + (mr + 8) * PITCH_H + kk + 8);
            }
#pragma unroll
            for (int nf = 0; nf < 8; ++nf) {
                const int nc = wn * 64 + nf * 8 + r;
                b[nf][0] = *reinterpret_cast<const uint32_t*>(Bs + nc * PITCH_H + kk    );
                b[nf][1] = *reinterpret_cast<const uint32_t*>(Bs + nc * PITCH_H + kk + 8);
            }
#pragma unroll
            for (int mi = 0; mi < 2; ++mi)
#pragma unroll
                for (int nf = 0; nf < 8; ++nf)
                    mma_bf16(acc[mi][nf], a[mi], b[nf]);
        }
        __syncthreads();     // everyone done reading cur before it is overwritten
    }

    // ---- epilogue: out[t][v] = acc + by[v]
#pragma unroll
    for (int mi = 0; mi < 2; ++mi) {
        const int v0 = m0 + wm * 32 + mi * 16 + r;
        const int v1 = v0 + 8;
        const float bias0 = (v0 < VOCAB) ? by[v0] : 0.f;
        const float bias1 = (v1 < VOCAB) ? by[v1] : 0.f;
#pragma unroll
        for (int nf = 0; nf < 8; ++nf) {
            const int t0 = wn * 64 + nf * 8 + c * 2;
            const int t1 = t0 + 1;
            if (v0 < VOCAB) {
                out[(size_t)t0 * VOCAB + v0] = acc[mi][nf][0] + bias0;
                out[(size_t)t1 * VOCAB + v0] = acc[mi][nf][1] + bias0;
            }
            if (v1 < VOCAB) {
                out[(size_t)t0 * VOCAB + v1] = acc[mi][nf][2] + bias1;
                out[(size_t)t1 * VOCAB + v1] = acc[mi][nf][3] + bias1;
            }
        }
    }
}

// ---------------- phase 3: softmax with smem exp cache (one expf pass, one global re-read saved)
#define SMAX_SMEM_BYTES (VOCAB * 4)   // 201028 B

extern __shared__ float s_exp[];

__global__ void __launch_bounds__(1024) softmax_rows_kernel(float* __restrict__ out) {
    __shared__ float red[1024];
    const int t = blockIdx.x;
    float* row = out + (size_t)t * VOCAB;
    const int tid = threadIdx.x;

    float m = -1e30f;
    for (int i = tid; i < VOCAB; i += 1024) m = fmaxf(m, row[i]);
    red[tid] = m; __syncthreads();
    for (int s = 512; s > 0; s >>= 1) {
        if (tid < s) red[tid] = fmaxf(red[tid], red[tid + s]);
        __syncthreads();
    }
    m = red[0];
    __syncthreads();

    float sum = 0.f;
    for (int i = tid; i < VOCAB; i += 1024) {
        float e = expf(row[i] - m);
        s_exp[i] = e;
        sum += e;
    }
    red[tid] = sum; __syncthreads();
    for (int s = 512; s > 0; s >>= 1) {
        if (tid < s) red[tid] += red[tid + s];
        __syncthreads();
    }
    float inv = 1.0f / red[0];
    __syncthreads();

    for (int i = tid; i < VOCAB; i += 1024) row[i] = s_exp[i] * inv;
}

// ---------------- launch ----------------
extern "C" void kernel_launch(void* const* d_in, const int* in_sizes, int n_in,
                              void* d_out, int out_size) {
    const int*   chars = (const int*)  d_in[0];
    const float* Wxh   = (const float*)d_in[1];
    const float* Whh   = (const float*)d_in[2];
    const float* Why   = (const float*)d_in[3];
    const float* bh    = (const float*)d_in[4];
    const float* by    = (const float*)d_in[5];
    const float* h0    = (const float*)d_in[6];
    float* out = (float*)d_out;

    cudaFuncSetAttribute(gemm_logits_kernel,
                         cudaFuncAttributeMaxDynamicSharedMemorySize, GEMM_SMEM_BYTES);
    cudaFuncSetAttribute(softmax_rows_kernel,
                         cudaFuncAttributeMaxDynamicSharedMemorySize, SMAX_SMEM_BYTES);

    init_kernel<<<1, 1024>>>();
    gather_x_kernel<<<dim3(TSTEPS, HDIM / 256), 256>>>(chars, Wxh, bh);
    rnn_steps_kernel<<<RNN_NB, RNN_THREADS>>>(Whh, h0);
    gemm_logits_kernel<<<(VOCAB + BM - 1) / BM, GEMM_THREADS, GEMM_SMEM_BYTES>>>(Why, by, out);
    softmax_rows_kernel<<<TSTEPS, 1024, SMAX_SMEM_BYTES>>>(out);
}

// round 8
// speedup vs baseline: 3.3422x; 1.0543x over previous
#include <cuda_runtime.h>
#include <cuda_bf16.h>
#include <math.h>
#include <stdint.h>

#define HDIM   1024
#define TSTEPS 256
#define VOCAB  50257

// ---------------- recurrence config ----------------
#define RNN_NB      64
#define RNN_THREADS 256
#define VEC_PER_BLK 3                        // 16 bf16 h = 8 u32 -> 3 vecs (3 u32 payload + tag)
#define NVEC        (RNN_NB * VEC_PER_BLK)   // 192  (<= 256 -> ONE poll per thread)
#define VEC_STRIDE  8                        // uint4 units: 128B -> own L2 line

// -------- device scratch (no allocations allowed) --------
__device__ __align__(16)  float g_X[TSTEPS * HDIM];            // Wxh[:, c_t] + bh
__device__ __align__(16)  __nv_bfloat16 g_Hb[TSTEPS * HDIM];   // hidden states (bf16)
__device__ __align__(128) uint4 g_pub[2 * NVEC * VEC_STRIDE];  // tagged h exchange

// ---- volatile 16B ld/st (single 128-bit transaction: tag+payload move together)
__device__ __forceinline__ uint4 ldv4u(const uint4* p) {
    uint4 v;
    asm volatile("ld.volatile.global.v4.u32 {%0,%1,%2,%3}, [%4];"
                 : "=r"(v.x), "=r"(v.y), "=r"(v.z), "=r"(v.w) : "l"(p));
    return v;
}
__device__ __forceinline__ void stv4u(uint4* p, uint4 v) {
    asm volatile("st.volatile.global.v4.u32 [%0], {%1,%2,%3,%4};"
                 :: "l"(p), "r"(v.x), "r"(v.y), "r"(v.z), "r"(v.w) : "memory");
}
__device__ __forceinline__ uint32_t pack_bf16(float lo, float hi) {
    __nv_bfloat162 v = __floats2bfloat162_rn(lo, hi);
    return *reinterpret_cast<uint32_t*>(&v);
}
__device__ __forceinline__ float bf16lo(uint32_t u) { return __uint_as_float(u << 16); }
__device__ __forceinline__ float bf16hi(uint32_t u) { return __uint_as_float(u & 0xFFFF0000u); }

// ---------------- init: clear exchange tags each launch (graph-replay determinism)
__global__ void init_kernel() {
    int i = blockIdx.x * blockDim.x + threadIdx.x;
    if (i < 2 * NVEC) g_pub[i * VEC_STRIDE].w = 0u;
}

// ---------------- gather: g_X[t][h] = Wxh[h][c_t] + bh[h]
__global__ void gather_x_kernel(const int* __restrict__ chars,
                                const float* __restrict__ Wxh,
                                const float* __restrict__ bh) {
    int t = blockIdx.x;
    int h = blockIdx.y * blockDim.x + threadIdx.x;
    int c = chars[t];
    g_X[t * HDIM + h] = Wxh[(size_t)h * VOCAB + c] + bh[h];
}

// ---------------- phase 1: recurrence, fence-free tagged exchange, bf16 payload.
// 64 blocks x 8 warps, 2 rows/warp. 3 vectors/block -> 192 total, 1 poll/thread.
__global__ void __launch_bounds__(RNN_THREADS, 1)
rnn_steps_kernel(const float* __restrict__ Whh, const float* __restrict__ h0) {
    __shared__ float sh[HDIM];          // h_{t-1} (fp32, expanded from bf16)
    __shared__ uint32_t hout_u[8];      // this block's 16 h as 8 bf16x2 words

    const int tid  = threadIdx.x;
    const int wid  = tid >> 5;
    const int lane = tid & 31;
    const int r0   = blockIdx.x * 16 + wid * 2;
    const int r1   = r0 + 1;

    float4 w0[8], w1[8];
    {
        const float4* p0 = reinterpret_cast<const float4*>(Whh + (size_t)r0 * HDIM);
        const float4* p1 = reinterpret_cast<const float4*>(Whh + (size_t)r1 * HDIM);
#pragma unroll
        for (int j = 0; j < 8; ++j) { w0[j] = p0[j * 32 + lane]; w1[j] = p1[j * 32 + lane]; }
    }

    reinterpret_cast<float4*>(sh)[tid] = reinterpret_cast<const float4*>(h0)[tid];
    __syncthreads();

    for (int t = 0; t < TSTEPS; ++t) {
        float x0 = 0.f, x1 = 0.f;
        if (lane == 0) {
            x0 = g_X[(size_t)t * HDIM + r0];
            x1 = g_X[(size_t)t * HDIM + r1];
        }

        float a0 = 0.f, a1 = 0.f;
#pragma unroll
        for (int j = 0; j < 8; ++j) {
            float4 hv = reinterpret_cast<const float4*>(sh)[j * 32 + lane];
            a0 += w0[j].x * hv.x + w0[j].y * hv.y + w0[j].z * hv.z + w0[j].w * hv.w;
            a1 += w1[j].x * hv.x + w1[j].y * hv.y + w1[j].z * hv.z + w1[j].w * hv.w;
        }
#pragma unroll
        for (int o = 16; o > 0; o >>= 1) {
            a0 += __shfl_down_sync(0xffffffffu, a0, o);
            a1 += __shfl_down_sync(0xffffffffu, a1, o);
        }

        if (lane == 0) {
            float h0v = tanhf(a0 + x0);
            float h1v = tanhf(a1 + x1);
            uint32_t pk = pack_bf16(h0v, h1v);
            *reinterpret_cast<uint32_t*>(g_Hb + (size_t)t * HDIM + r0) = pk;  // GEMM input
            hout_u[wid] = pk;
        }

        if (t + 1 < TSTEPS) {
            const uint32_t tag = (uint32_t)(t + 1);
            __syncthreads();   // hout_u complete; everyone done reading sh

            // publish: 3 tagged vectors (3 bf16x2 words + tag), parity buffer
            if (tid < VEC_PER_BLK) {
                const int j = tid;
                uint4 v;
                v.x = hout_u[3 * j];
                v.y = hout_u[(3 * j + 1 < 8) ? 3 * j + 1 : 7];
                v.z = hout_u[(3 * j + 2 < 8) ? 3 * j + 2 : 7];
                v.w = tag;
                stv4u(&g_pub[((t & 1) * NVEC + blockIdx.x * VEC_PER_BLK + j) * VEC_STRIDE], v);
            }

            // poll: exactly one vector per thread (192 of 256 threads)
            if (tid < NVEC) {
                const uint4* base = &g_pub[(t & 1) * NVEC * VEC_STRIDE];
                uint4 v;
                do { v = ldv4u(base + tid * VEC_STRIDE); } while (v.w != tag);
                const int b = tid / VEC_PER_BLK, j = tid % VEC_PER_BLK;
                const int bs = b * 16, w0i = 3 * j;
                sh[bs + 2 * w0i]     = bf16lo(v.x);
                sh[bs + 2 * w0i + 1] = bf16hi(v.x);
                if (w0i + 1 < 8) {
                    sh[bs + 2 * w0i + 2] = bf16lo(v.y);
                    sh[bs + 2 * w0i + 3] = bf16hi(v.y);
                }
                if (w0i + 2 < 8) {
                    sh[bs + 2 * w0i + 4] = bf16lo(v.z);
                    sh[bs + 2 * w0i + 5] = bf16hi(v.z);
                }
            }
            __syncthreads();   // sh = h_t complete
        }
    }
}

// ---------------- phase 2: bf16 mma.sync GEMM, single-sync double-buffered pipeline
// logits[t][v] = sum_k Why[v][k] * H[t][k] + by[v]
#define BM 128
#define BN 256
#define BK 32
#define GEMM_THREADS 512
#define PITCH_H 40                            // bf16 per smem row: conflict-free + 16B aligned
#define A_TILE_H (BM * PITCH_H)
#define B_TILE_H (BN * PITCH_H)
#define STAGE_H  (A_TILE_H + B_TILE_H)
#define GEMM_SMEM_BYTES (2 * STAGE_H * 2)     // 61440 B

__device__ __forceinline__ void cp16(uint32_t sdst, const void* gsrc) {
    asm volatile("cp.async.cg.shared.global [%0], [%1], 16;\n" :: "r"(sdst), "l"(gsrc));
}
__device__ __forceinline__ void cp_commit() {
    asm volatile("cp.async.commit_group;\n");
}
__device__ __forceinline__ void cp_wait0() {
    asm volatile("cp.async.wait_group 0;\n");
}

__device__ __forceinline__ void mma_bf16(float d[4], const uint32_t a[4], const uint32_t b[2]) {
    asm volatile(
        "mma.sync.aligned.m16n8k16.row.col.f32.bf16.bf16.f32 "
        "{%0,%1,%2,%3}, {%4,%5,%6,%7}, {%8,%9}, {%0,%1,%2,%3};\n"
        : "+f"(d[0]), "+f"(d[1]), "+f"(d[2]), "+f"(d[3])
        : "r"(a[0]), "r"(a[1]), "r"(a[2]), "r"(a[3]), "r"(b[0]), "r"(b[1]));
}

extern __shared__ __nv_bfloat16 g_smem[];

__global__ void __launch_bounds__(GEMM_THREADS, 1)
gemm_logits_kernel(const float* __restrict__ Why,
                   const float* __restrict__ by,
                   float* __restrict__ out) {
    const int tid  = threadIdx.x;
    const int lane = tid & 31;
    const int wid  = tid >> 5;
    const int wm   = wid & 3;        // warp m (0..3) -> 32 vocab rows
    const int wn   = wid >> 2;       // warp n (0..3) -> 64 time cols
    const int m0   = blockIdx.x * BM;

    const uint32_t smem_u = (uint32_t)__cvta_generic_to_shared(g_smem);

    // A (Why) LDG mapping: thread -> (row, k-chunk of 8 fp32)
    const int arow = tid >> 2;
    const int ak0  = (tid & 3) * 8;
    int agm = m0 + arow; if (agm > VOCAB - 1) agm = VOCAB - 1;
    const float4* Aptr = reinterpret_cast<const float4*>(Why + (size_t)agm * HDIM + ak0);

    auto load_B = [&](int stage, int k0) {
        uint32_t sb = smem_u + (uint32_t)(stage * STAGE_H + A_TILE_H) * 2u;
#pragma unroll
        for (int q = 0; q < 2; ++q) {
            int i = tid + q * GEMM_THREADS;
            int row = i >> 2, ch = i & 3;
            cp16(sb + (uint32_t)(row * PITCH_H + ch * 8) * 2u,
                 g_Hb + (size_t)row * HDIM + k0 + ch * 8);
        }
        cp_commit();
    };

    float acc[2][8][4] = {};

    // prologue: A regs + B cp.async for kt=0
    float4 fa = Aptr[0];
    float4 fb = Aptr[1];
    load_B(0, 0);

    const int r = lane >> 2;
    const int c = lane & 3;

    for (int kt = 0; kt < HDIM / BK; ++kt) {
        const int cur = kt & 1;
        __nv_bfloat16* As = g_smem + cur * STAGE_H;
        const __nv_bfloat16* Bs = As + A_TILE_H;

        // STS this kt's A (one STS.128); buffer cur last read at kt-2, safe since sync(kt-1)
        {
            uint4 p;
            p.x = pack_bf16(fa.x, fa.y);
            p.y = pack_bf16(fa.z, fa.w);
            p.z = pack_bf16(fb.x, fb.y);
            p.w = pack_bf16(fb.z, fb.w);
            *reinterpret_cast<uint4*>(As + arow * PITCH_H + ak0) = p;
        }
        // next A LDG issued before the wait (overlaps)
        if (kt + 1 < HDIM / BK) {
            const float4* An = Aptr + (kt + 1) * (BK / 4);
            fa = An[0];
            fb = An[1];
        }

        cp_wait0();          // B(cur) resident (only group in flight)
        __syncthreads();     // A(cur)+B(cur) visible; gates all buffer reuse

        if (kt + 1 < HDIM / BK)
            load_B(cur ^ 1, (kt + 1) * BK);   // overlaps with mma below

        // mma: 2 ki of k=16
#pragma unroll
        for (int ki = 0; ki < 2; ++ki) {
            uint32_t a[2][4], b[8][2];
            const int kk = ki * 16 + 2 * c;
#pragma unroll
            for (int mi = 0; mi < 2; ++mi) {
                const int mr = wm * 32 + mi * 16 + r;
                a[mi][0] = *reinterpret_cast<const uint32_t*>(As + (mr    ) * PITCH_H + kk    );
                a[mi][1] = *reinterpret_cast<const uint32_t*>(As + (mr + 8) * PITCH_H + kk    );
                a[mi][2] = *reinterpret_cast<const uint32_t*>(As + (mr    ) * PITCH_H + kk + 8);
                a[mi][3] = *reinterpret_cast<const uint32_t*>(As + (mr + 8) * PITCH_H + kk + 8);
            }
#pragma unroll
            for (int nf = 0; nf < 8; ++nf) {
                const int nc = wn * 64 + nf * 8 + r;
                b[nf][0] = *reinterpret_cast<const uint32_t*>(Bs + nc * PITCH_H + kk    );
                b[nf][1] = *reinterpret_cast<const uint32_t*>(Bs + nc * PITCH_H + kk + 8);
            }
#pragma unroll
            for (int mi = 0; mi < 2; ++mi)
#pragma unroll
                for (int nf = 0; nf < 8; ++nf)
                    mma_bf16(acc[mi][nf], a[mi], b[nf]);
        }
        // no trailing sync: next iteration's sync gates reuse
    }

    // ---- epilogue: out[t][v] = acc + by[v]
#pragma unroll
    for (int mi = 0; mi < 2; ++mi) {
        const int v0 = m0 + wm * 32 + mi * 16 + r;
        const int v1 = v0 + 8;
        const float bias0 = (v0 < VOCAB) ? by[v0] : 0.f;
        const float bias1 = (v1 < VOCAB) ? by[v1] : 0.f;
#pragma unroll
        for (int nf = 0; nf < 8; ++nf) {
            const int t0 = wn * 64 + nf * 8 + c * 2;
            const int t1 = t0 + 1;
            if (v0 < VOCAB) {
                out[(size_t)t0 * VOCAB + v0] = acc[mi][nf][0] + bias0;
                out[(size_t)t1 * VOCAB + v0] = acc[mi][nf][1] + bias0;
            }
            if (v1 < VOCAB) {
                out[(size_t)t0 * VOCAB + v1] = acc[mi][nf][2] + bias1;
                out[(size_t)t1 * VOCAB + v1] = acc[mi][nf][3] + bias1;
            }
        }
    }
}

// ---------------- phase 3: softmax with smem exp cache
#define SMAX_SMEM_BYTES (VOCAB * 4)

extern __shared__ float s_exp[];

__global__ void __launch_bounds__(1024) softmax_rows_kernel(float* __restrict__ out) {
    __shared__ float red[1024];
    const int t = blockIdx.x;
    float* row = out + (size_t)t * VOCAB;
    const int tid = threadIdx.x;

    float m = -1e30f;
    for (int i = tid; i < VOCAB; i += 1024) m = fmaxf(m, row[i]);
    red[tid] = m; __syncthreads();
    for (int s = 512; s > 0; s >>= 1) {
        if (tid < s) red[tid] = fmaxf(red[tid], red[tid + s]);
        __syncthreads();
    }
    m = red[0];
    __syncthreads();

    float sum = 0.f;
    for (int i = tid; i < VOCAB; i += 1024) {
        float e = expf(row[i] - m);
        s_exp[i] = e;
        sum += e;
    }
    red[tid] = sum; __syncthreads();
    for (int s = 512; s > 0; s >>= 1) {
        if (tid < s) red[tid] += red[tid + s];
        __syncthreads();
    }
    float inv = 1.0f / red[0];
    __syncthreads();

    for (int i = tid; i < VOCAB; i += 1024) row[i] = s_exp[i] * inv;
}

// ---------------- launch ----------------
extern "C" void kernel_launch(void* const* d_in, const int* in_sizes, int n_in,
                              void* d_out, int out_size) {
    const int*   chars = (const int*)  d_in[0];
    const float* Wxh   = (const float*)d_in[1];
    const float* Whh   = (const float*)d_in[2];
    const float* Why   = (const float*)d_in[3];
    const float* bh    = (const float*)d_in[4];
    const float* by    = (const float*)d_in[5];
    const float* h0    = (const float*)d_in[6];
    float* out = (float*)d_out;

    cudaFuncSetAttribute(gemm_logits_kernel,
                         cudaFuncAttributeMaxDynamicSharedMemorySize, GEMM_SMEM_BYTES);
    cudaFuncSetAttribute(softmax_rows_kernel,
                         cudaFuncAttributeMaxDynamicSharedMemorySize, SMAX_SMEM_BYTES);

    init_kernel<<<1, 1024>>>();
    gather_x_kernel<<<dim3(TSTEPS, HDIM / 256), 256>>>(chars, Wxh, bh);
    rnn_steps_kernel<<<RNN_NB, RNN_THREADS>>>(Whh, h0);
    gemm_logits_kernel<<<(VOCAB + BM - 1) / BM, GEMM_THREADS, GEMM_SMEM_BYTES>>>(Why, by, out);
    softmax_rows_kernel<<<TSTEPS, 1024, SMAX_SMEM_BYTES>>>(out);
}